// round 2
// baseline (speedup 1.0000x reference)
#include <cuda_runtime.h>

// CollisionLoss: sum over (f, n) of clipped AABB intersection between the SDC
// box (per-frame, from trajectory + heading) and each GT box's AABB, masked.
//
// inputs (metadata order):
//  d_in[0] sdc_traj_all        (1, F, 2) f32   -> x, y per frame
//  d_in[1] sdc_planning_gt     (1, F, 3) f32   -> theta = [..., 2]
//  d_in[2] sdc_planning_gt_mask (unused by reference)
//  d_in[3] future_gt_corners   (F, N, 4, 2) f32  [dominant: 192 MB]
//  d_in[4] box_mask            (F, N) bool -> materialized as int32 (R1 finding)
// output: 1 x f32 scalar

#define F_FRAMES 6
#define N_PTS    1000000
#define TOTAL    (F_FRAMES * N_PTS)
#define W_BOX    2.35f    /* 1.85 + 0.5 */
#define H_BOX    4.584f   /* 4.084 + 0.5 */

#define NTHREADS 256
#define NBLOCKS  2368     /* 148 SMs * 16 */

__device__ float4 g_box[F_FRAMES];       // (xmax, ymax, xmin, ymin) per frame
__device__ float  g_partial[NBLOCKS];

__global__ void sdc_box_kernel(const float* __restrict__ traj,
                               const float* __restrict__ gt)
{
    int f = threadIdx.x;
    if (f < F_FRAMES) {
        float x  = traj[f * 2 + 0];
        float y  = traj[f * 2 + 1];
        float th = gt[f * 3 + 2];
        float c, s;
        __sincosf(th, &s, &c);
        const float hw = W_BOX * 0.5f;
        const float hh = H_BOX * 0.5f;
        const float lx[4] = { hw,  hw, -hw, -hw };
        const float ly[4] = {-hh,  hh,  hh, -hh };
        float xmax = -1e30f, xmin = 1e30f, ymax = -1e30f, ymin = 1e30f;
#pragma unroll
        for (int k = 0; k < 4; k++) {
            // corners[f,k,i] = sum_j rot[f,i,j] * local[k,j]; rot = [[c,s],[-s,c]]
            float cx =  c * lx[k] + s * ly[k] + x;
            float cy = -s * lx[k] + c * ly[k] + y;
            xmax = fmaxf(xmax, cx); xmin = fminf(xmin, cx);
            ymax = fmaxf(ymax, cy); ymin = fminf(ymin, cy);
        }
        g_box[f] = make_float4(xmax, ymax, xmin, ymin);
    }
}

__global__ __launch_bounds__(NTHREADS)
void collision_main_kernel(const float4* __restrict__ corners,
                           const int* __restrict__ mask)
{
    __shared__ float4 sbox[F_FRAMES];
    if (threadIdx.x < F_FRAMES) sbox[threadIdx.x] = g_box[threadIdx.x];
    __syncthreads();

    float acc = 0.0f;
    const unsigned stride = gridDim.x * blockDim.x;
    for (unsigned item = blockIdx.x * blockDim.x + threadIdx.x;
         item < TOTAL; item += stride) {
        // 8 floats per item: (x0,y0,x1,y1),(x2,y2,x3,y3)
        float4 c0 = corners[item * 2u + 0u];
        float4 c1 = corners[item * 2u + 1u];
        int m = mask[item];
        unsigned f = item / (unsigned)N_PTS;   // mul-high, cheap
        float4 b = sbox[f];

        float xb1 = fmaxf(fmaxf(c0.x, c0.z), fmaxf(c1.x, c1.z));
        float xb2 = fminf(fminf(c0.x, c0.z), fminf(c1.x, c1.z));
        float yb1 = fmaxf(fmaxf(c0.y, c0.w), fmaxf(c1.y, c1.w));
        float yb2 = fminf(fminf(c0.y, c0.w), fminf(c1.y, c1.w));

        float w = fmaxf(0.0f, fminf(b.x, xb1) - fmaxf(b.z, xb2));
        float h = fmaxf(0.0f, fminf(b.y, yb1) - fmaxf(b.w, yb2));
        acc += m ? (w * h) : 0.0f;
    }

    // warp reduce
#pragma unroll
    for (int o = 16; o > 0; o >>= 1)
        acc += __shfl_down_sync(0xffffffffu, acc, o);

    __shared__ float ws[NTHREADS / 32];
    if ((threadIdx.x & 31) == 0) ws[threadIdx.x >> 5] = acc;
    __syncthreads();
    if (threadIdx.x < 32) {
        float v = (threadIdx.x < NTHREADS / 32) ? ws[threadIdx.x] : 0.0f;
#pragma unroll
        for (int o = 4; o > 0; o >>= 1)
            v += __shfl_down_sync(0xffffffffu, v, o);
        if (threadIdx.x == 0) g_partial[blockIdx.x] = v;
    }
}

__global__ __launch_bounds__(NTHREADS)
void final_reduce_kernel(float* __restrict__ out)
{
    float acc = 0.0f;
    for (int i = threadIdx.x; i < NBLOCKS; i += NTHREADS)
        acc += g_partial[i];
#pragma unroll
    for (int o = 16; o > 0; o >>= 1)
        acc += __shfl_down_sync(0xffffffffu, acc, o);

    __shared__ float ws[NTHREADS / 32];
    if ((threadIdx.x & 31) == 0) ws[threadIdx.x >> 5] = acc;
    __syncthreads();
    if (threadIdx.x == 0) {
        float v = 0.0f;
#pragma unroll
        for (int i = 0; i < NTHREADS / 32; i++) v += ws[i];
        out[0] = v * 1.0f;  // WEIGHT = 1.0
    }
}

extern "C" void kernel_launch(void* const* d_in, const int* in_sizes, int n_in,
                              void* d_out, int out_size)
{
    const float* traj = (const float*)d_in[0];
    const float* gt   = (const float*)d_in[1];
    const float4* corners = (const float4*)d_in[3];
    const int* mask = (const int*)d_in[4];
    float* out = (float*)d_out;

    sdc_box_kernel<<<1, 32>>>(traj, gt);
    collision_main_kernel<<<NBLOCKS, NTHREADS>>>(corners, mask);
    final_reduce_kernel<<<1, NTHREADS>>>(out);
}